// round 5
// baseline (speedup 1.0000x reference)
#include <cuda_runtime.h>
#include <cuda_bf16.h>
#include <cstdint>

#define SEQ     2048
#define BATCH   2
#define HIDDEN  1024
#define NHEAD   16
#define HDIM    64
#define NH      32
#define TOK     4096

// Scratch (device globals). All values tf32-rounded by the QKV epilogue.
__device__ float g_q[(size_t)NH * SEQ * HDIM];   // [n][s][d]
__device__ float g_k[(size_t)NH * HDIM * SEQ];   // [n][d][s]
__device__ float g_v[(size_t)NH * HDIM * SEQ];   // [n][d][s]

// ---------------------------------------------------------------- helpers
__device__ __forceinline__ float tf32f(float x) {
    uint32_t r; asm("cvt.rna.tf32.f32 %0, %1;" : "=r"(r) : "f"(x));
    return __uint_as_float(r);
}
__device__ __forceinline__ uint32_t tf32u(float x) {
    uint32_t r; asm("cvt.rna.tf32.f32 %0, %1;" : "=r"(r) : "f"(x));
    return r;
}
__device__ __forceinline__ float ex2f(float x) {
    float y; asm("ex2.approx.ftz.f32 %0, %1;" : "=f"(y) : "f"(x));
    return y;
}
__device__ __forceinline__ uint32_t packbf(float lo, float hi) {
    uint32_t r; asm("cvt.rn.bf16x2.f32 %0, %1, %2;" : "=r"(r) : "f"(hi), "f"(lo));
    return r;
}
__device__ __forceinline__ float bfhi(float x) {   // bf16-rounded value of x
    return __bfloat162float(__float2bfloat16_rn(x));
}
// m16n8k8 tf32: D += A*B (A row-major 4 regs, B col-major 2 regs)
__device__ __forceinline__ void mma8(float d[4], const uint32_t a[4],
                                     uint32_t b0, uint32_t b1) {
    asm volatile(
        "mma.sync.aligned.m16n8k8.row.col.f32.tf32.tf32.f32 "
        "{%0,%1,%2,%3}, {%4,%5,%6,%7}, {%8,%9}, {%0,%1,%2,%3};"
        : "+f"(d[0]), "+f"(d[1]), "+f"(d[2]), "+f"(d[3])
        : "r"(a[0]), "r"(a[1]), "r"(a[2]), "r"(a[3]), "r"(b0), "r"(b1));
}
// m16n8k16 bf16: D += A*B
__device__ __forceinline__ void mma16bf(float d[4], const uint32_t a[4],
                                        uint32_t b0, uint32_t b1) {
    asm volatile(
        "mma.sync.aligned.m16n8k16.row.col.f32.bf16.bf16.f32 "
        "{%0,%1,%2,%3}, {%4,%5,%6,%7}, {%8,%9}, {%0,%1,%2,%3};"
        : "+f"(d[0]), "+f"(d[1]), "+f"(d[2]), "+f"(d[3])
        : "r"(a[0]), "r"(a[1]), "r"(a[2]), "r"(a[3]), "r"(b0), "r"(b1));
}
__device__ __forceinline__ uint32_t smem_u32(const void* p) {
    uint32_t a;
    asm("{ .reg .u64 t; cvta.to.shared.u64 t, %1; cvt.u32.u64 %0, t; }" : "=r"(a) : "l"(p));
    return a;
}
__device__ __forceinline__ void cpa16(uint32_t s, const void* g) {
    asm volatile("cp.async.ca.shared.global [%0], [%1], 16;" :: "r"(s), "l"(g));
}
#define CPA_COMMIT() asm volatile("cp.async.commit_group;" ::: "memory")
#define CPA_WAIT(n)  asm volatile("cp.async.wait_group %0;" :: "n"(n) : "memory")

// ---------------------------------------------------------------- QKV GEMM
// C[t][c] = sum_k hs[t][k]*W[k][c] + bias[c].  CTA tile 256x128, BK=32,
// cp.async double-buffered. 8 warps 4(M)x2(N), warp tile 64x64.
#define QKV_BUFW  (256 * 36 + 32 * 136)     // words per stage
#define QKV_SMEM  (2 * QKV_BUFW * 4)

__global__ __launch_bounds__(256, 1) void qkv_kernel(
    const float* __restrict__ hs,
    const float* __restrict__ Wq, const float* __restrict__ bq,
    const float* __restrict__ Wk, const float* __restrict__ bk,
    const float* __restrict__ Wv, const float* __restrict__ bv)
{
    extern __shared__ float smq[];
    const uint32_t sbase = smem_u32(smq);

    const int z = blockIdx.z;
    const float* W    = (z == 0) ? Wq : (z == 1) ? Wk : Wv;
    const float* bias = (z == 0) ? bq : (z == 1) ? bk : bv;

    const int tid = threadIdx.x;
    const int lane = tid & 31, wid = tid >> 5;
    const int wm = wid >> 1, wn = wid & 1;
    const int c0 = blockIdx.x * 128;
    const int t0 = blockIdx.y * 256;
    const int r = lane >> 2, cq = lane & 3;

    float acc[4][8][4];
#pragma unroll
    for (int i = 0; i < 4; i++)
#pragma unroll
        for (int j = 0; j < 8; j++)
#pragma unroll
            for (int k = 0; k < 4; k++) acc[i][j][k] = 0.f;

    auto issue = [&](int t, int b) {
        const uint32_t ab = sbase + (uint32_t)b * QKV_BUFW * 4;
        const uint32_t bb = ab + 256 * 36 * 4;
#pragma unroll
        for (int j = 0; j < 8; j++) {
            int idx = tid + j * 256;
            int row = idx >> 3, c4 = (idx & 7) * 4;
            cpa16(ab + (row * 36 + c4) * 4,
                  hs + (size_t)(t0 + row) * HIDDEN + t * 32 + c4);
        }
#pragma unroll
        for (int j = 0; j < 4; j++) {
            int idx = tid + j * 256;
            int row = idx >> 5, c4 = (idx & 31) * 4;
            cpa16(bb + (row * 136 + c4) * 4,
                  W + (size_t)(t * 32 + row) * HIDDEN + c0 + c4);
        }
        CPA_COMMIT();
    };

    issue(0, 0);
    for (int t = 0; t < 32; t++) {
        const int b = t & 1;
        if (t < 31) { issue(t + 1, 1 - b); CPA_WAIT(1); }
        else        { CPA_WAIT(0); }
        __syncthreads();

        const float* A = smq + b * QKV_BUFW;
        const float* B = A + 256 * 36;
#pragma unroll
        for (int ks = 0; ks < 4; ks++) {
            const int kk = ks * 8;
            uint32_t af[4][4], bf[8][2];
#pragma unroll
            for (int mt = 0; mt < 4; mt++) {
                int m = wm * 64 + mt * 16 + r;
                af[mt][0] = tf32u(A[m * 36 + kk + cq]);
                af[mt][1] = tf32u(A[(m + 8) * 36 + kk + cq]);
                af[mt][2] = tf32u(A[m * 36 + kk + cq + 4]);
                af[mt][3] = tf32u(A[(m + 8) * 36 + kk + cq + 4]);
            }
#pragma unroll
            for (int nf = 0; nf < 8; nf++) {
                int nn = wn * 64 + nf * 8 + r;
                bf[nf][0] = tf32u(B[(kk + cq) * 136 + nn]);
                bf[nf][1] = tf32u(B[(kk + cq + 4) * 136 + nn]);
            }
#pragma unroll
            for (int mt = 0; mt < 4; mt++)
#pragma unroll
                for (int nf = 0; nf < 8; nf++)
                    mma8(acc[mt][nf], af[mt], bf[nf][0], bf[nf][1]);
        }
        __syncthreads();
    }

    const int c2 = cq * 2;
#pragma unroll
    for (int mt = 0; mt < 4; mt++) {
#pragma unroll
        for (int hf = 0; hf < 2; hf++) {
            int t = t0 + wm * 64 + mt * 16 + hf * 8 + r;
            int s = t >> 1, bb = t & 1;
#pragma unroll
            for (int nf = 0; nf < 8; nf++) {
                int cc = c0 + wn * 64 + nf * 8 + c2;
                int h = cc >> 6, d = cc & 63;
                int nH = bb * NHEAD + h;
                float v0 = tf32f(acc[mt][nf][hf * 2 + 0] + bias[cc]);
                float v1 = tf32f(acc[mt][nf][hf * 2 + 1] + bias[cc + 1]);
                if (z == 0) {
                    *(float2*)(g_q + ((size_t)nH * SEQ + s) * HDIM + d) =
                        make_float2(v0, v1);
                } else {
                    float* dst = (z == 1) ? g_k : g_v;
                    dst[((size_t)nH * HDIM + d) * SEQ + s]     = v0;
                    dst[((size_t)nH * HDIM + d + 1) * SEQ + s] = v1;
                }
            }
        }
    }
}

// ---------------------------------------------------------------- attention
// CTA = 128 threads (4 warps), q-tile 64, k-tile 64, head n.
// Warp w owns q rows [16w,16w+16) x all 64 k-cols, so S accumulators map
// directly to bf16 A fragments: P stays in registers.
// PV uses SPLIT-BF16 (hi+lo) on both P and V: PhVh + PhVl + PlVh, giving
// ~2^-18 operand precision (better than tf32) at bf16 MMA rates.
#define AK_ST 72    // Ks stride (fp32 words)
#define AV_ST 136   // Vh/Vl stride (bf16 elems)

__global__ __launch_bounds__(128, 2) void attn_kernel(
    const float* __restrict__ mask, float* __restrict__ out)
{
    __shared__ float Ks[64 * AK_ST];
    __shared__ __nv_bfloat16 Vh[64 * AV_ST];
    __shared__ __nv_bfloat16 Vl[64 * AV_ST];

    const int n  = blockIdx.x;          // head-instance (b*16+h)
    const int q0 = blockIdx.y * 64;
    const int b = n >> 4, h = n & 15;
    const int tid = threadIdx.x;
    const int lane = tid & 31, wid = tid >> 5;
    const int r = lane >> 2, cq = lane & 3;
    const int m = wid * 16 + r;         // local q row (and +8)

    const float* qg = g_q + (size_t)n * SEQ * HDIM;
    const float* kg = g_k + (size_t)n * HDIM * SEQ;
    const float* vg = g_v + (size_t)n * HDIM * SEQ;

    // Q fragments, register-resident (values already tf32-rounded).
    uint32_t qf[8][4];
#pragma unroll
    for (int kg8 = 0; kg8 < 8; kg8++) {
        const int kk = kg8 * 8;
        qf[kg8][0] = __float_as_uint(qg[(size_t)(q0 + m) * HDIM + kk + cq]);
        qf[kg8][1] = __float_as_uint(qg[(size_t)(q0 + m + 8) * HDIM + kk + cq]);
        qf[kg8][2] = __float_as_uint(qg[(size_t)(q0 + m) * HDIM + kk + cq + 4]);
        qf[kg8][3] = __float_as_uint(qg[(size_t)(q0 + m + 8) * HDIM + kk + cq + 4]);
    }

    float o[8][4];
#pragma unroll
    for (int i = 0; i < 8; i++)
#pragma unroll
        for (int j = 0; j < 4; j++) o[i][j] = 0.f;
    float l0 = 0.f, l1 = 0.f;

    const float C1 = 0.18033688011112042f;   // log2(e)/8
    const float C2 = 1.4426950408889634f;    // log2(e)
    const float* mrow0 = mask + ((size_t)b * SEQ + q0 + m) * SEQ;
    const float* mrow1 = mrow0 + 8 * SEQ;

    for (int kt = 0; kt < SEQ / 64; kt++) {
        const int k0 = kt * 64;
        __syncthreads();
        // K tile: Ks[d][s] fp32
#pragma unroll
        for (int j = 0; j < 8; j++) {
            int idx = tid + j * 128;
            int row = idx >> 4, c4 = (idx & 15) * 4;
            *(float4*)(Ks + row * AK_ST + c4) =
                *(const float4*)(kg + (size_t)row * SEQ + k0 + c4);
        }
        // V tile: split into Vh (bf16) + Vl (residual bf16)
#pragma unroll
        for (int j = 0; j < 8; j++) {
            int idx = tid + j * 128;
            int row = idx >> 4, c4 = (idx & 15) * 4;
            float4 v = *(const float4*)(vg + (size_t)row * SEQ + k0 + c4);
            float hx = bfhi(v.x), hy = bfhi(v.y), hz = bfhi(v.z), hw = bfhi(v.w);
            uint2 ph = make_uint2(packbf(hx, hy), packbf(hz, hw));
            uint2 pl = make_uint2(packbf(v.x - hx, v.y - hy),
                                  packbf(v.z - hz, v.w - hw));
            *(uint2*)((char*)Vh + row * (AV_ST * 2) + c4 * 2) = ph;
            *(uint2*)((char*)Vl + row * (AV_ST * 2) + c4 * 2) = pl;
        }
        __syncthreads();

        // mma1: S[16][64] = Q . K^T  (tf32, reduction over d=64)
        float s[8][4];
#pragma unroll
        for (int i = 0; i < 8; i++)
#pragma unroll
            for (int j = 0; j < 4; j++) s[i][j] = 0.f;
#pragma unroll
        for (int kg8 = 0; kg8 < 8; kg8++) {
            const int kk = kg8 * 8;
#pragma unroll
            for (int nt = 0; nt < 8; nt++) {
                int nn = nt * 8 + r;
                uint32_t b0 = __float_as_uint(Ks[(kk + cq) * AK_ST + nn]);
                uint32_t b1 = __float_as_uint(Ks[(kk + cq + 4) * AK_ST + nn]);
                mma8(s[nt], qf[kg8], b0, b1);
            }
        }

        // softmax (max-free) + split-bf16 P fragments (register-resident)
        uint32_t pah[4][4], pal[4][4];
#pragma unroll
        for (int nt = 0; nt < 8; nt++) {
            const int col = k0 + nt * 8 + cq * 2;
            float2 mk0 = *(const float2*)(mrow0 + col);
            float2 mk1 = *(const float2*)(mrow1 + col);
            float p0 = ex2f(s[nt][0] * C1 + mk0.x * C2);
            float p1 = ex2f(s[nt][1] * C1 + mk0.y * C2);
            float p2 = ex2f(s[nt][2] * C1 + mk1.x * C2);
            float p3 = ex2f(s[nt][3] * C1 + mk1.y * C2);
            l0 += p0 + p1;
            l1 += p2 + p3;
            float h0 = bfhi(p0), h1 = bfhi(p1), h2 = bfhi(p2), h3 = bfhi(p3);
            const int g = nt >> 1, o2 = (nt & 1) * 2;
            pah[g][o2 + 0] = packbf(h0, h1);
            pah[g][o2 + 1] = packbf(h2, h3);
            pal[g][o2 + 0] = packbf(p0 - h0, p1 - h1);
            pal[g][o2 + 1] = packbf(p2 - h2, p3 - h3);
        }

        // mma2: O += P . V  via PhVh + PhVl + PlVh (reduction over k=64)
#pragma unroll
        for (int kg2 = 0; kg2 < 4; kg2++) {
            const int kk = kg2 * 16;
#pragma unroll
            for (int nt = 0; nt < 8; nt++) {
                int dd = nt * 8 + r;
                const char* vrh = (const char*)Vh + dd * (AV_ST * 2);
                const char* vrl = (const char*)Vl + dd * (AV_ST * 2);
                uint32_t bh0 = *(const uint32_t*)(vrh + kk * 2 + cq * 4);
                uint32_t bh1 = *(const uint32_t*)(vrh + (kk + 8) * 2 + cq * 4);
                uint32_t bl0 = *(const uint32_t*)(vrl + kk * 2 + cq * 4);
                uint32_t bl1 = *(const uint32_t*)(vrl + (kk + 8) * 2 + cq * 4);
                mma16bf(o[nt], pah[kg2], bh0, bh1);
                mma16bf(o[nt], pah[kg2], bl0, bl1);
                mma16bf(o[nt], pal[kg2], bh0, bh1);
            }
        }
    }

    // Row sums: quad reduce, normalize, store.
    l0 += __shfl_xor_sync(0xffffffffu, l0, 1);
    l0 += __shfl_xor_sync(0xffffffffu, l0, 2);
    l1 += __shfl_xor_sync(0xffffffffu, l1, 1);
    l1 += __shfl_xor_sync(0xffffffffu, l1, 2);
    const float inv0 = 1.0f / l0, inv1 = 1.0f / l1;
    const int qr0 = q0 + m, qr1 = qr0 + 8;
#pragma unroll
    for (int nt = 0; nt < 8; nt++) {
        int dd = nt * 8 + cq * 2;
        *(float2*)(out + ((size_t)qr0 * BATCH + b) * HIDDEN + h * HDIM + dd) =
            make_float2(o[nt][0] * inv0, o[nt][1] * inv0);
        *(float2*)(out + ((size_t)qr1 * BATCH + b) * HIDDEN + h * HDIM + dd) =
            make_float2(o[nt][2] * inv1, o[nt][3] * inv1);
    }
}

// ----------------------------------------------------------------
extern "C" void kernel_launch(void* const* d_in, const int* in_sizes, int n_in,
                              void* d_out, int out_size)
{
    const float* hs   = (const float*)d_in[0];
    const float* mask = (const float*)d_in[1];
    const float* Wq   = (const float*)d_in[2];
    const float* bq   = (const float*)d_in[3];
    const float* Wk   = (const float*)d_in[4];
    const float* bk   = (const float*)d_in[5];
    const float* Wv   = (const float*)d_in[6];
    const float* bv   = (const float*)d_in[7];
    float* out = (float*)d_out;

    cudaFuncSetAttribute(qkv_kernel,
                         cudaFuncAttributeMaxDynamicSharedMemorySize, QKV_SMEM);

    dim3 g1(HIDDEN / 128, TOK / 256, 3);
    qkv_kernel<<<g1, 256, QKV_SMEM>>>(hs, Wq, bq, Wk, bk, Wv, bv);

    dim3 g2(NH, SEQ / 64);
    attn_kernel<<<g2, 128>>>(mask, out);
}

// round 6
// speedup vs baseline: 1.0026x; 1.0026x over previous
#include <cuda_runtime.h>
#include <cuda_bf16.h>
#include <cstdint>

#define SEQ     2048
#define BATCH   2
#define HIDDEN  1024
#define NHEAD   16
#define HDIM    64
#define NH      32
#define TOK     4096

// Scratch (device globals).
__device__ float g_hs[(size_t)TOK * HIDDEN];            // hs, tf32-rounded
__device__ float g_w[3][HIDDEN * HIDDEN];               // W, tf32-rounded
__device__ float g_q[(size_t)NH * SEQ * HDIM];          // [n][s][d] tf32
__device__ float g_k[(size_t)NH * HDIM * SEQ];          // [n][d][s] tf32
__device__ __nv_bfloat16 g_vh[(size_t)NH * HDIM * SEQ]; // V hi, [n][d][s]
__device__ __nv_bfloat16 g_vl[(size_t)NH * HDIM * SEQ]; // V lo residual

// ---------------------------------------------------------------- helpers
__device__ __forceinline__ float tf32f(float x) {
    uint32_t r; asm("cvt.rna.tf32.f32 %0, %1;" : "=r"(r) : "f"(x));
    return __uint_as_float(r);
}
__device__ __forceinline__ float ex2f(float x) {
    float y; asm("ex2.approx.ftz.f32 %0, %1;" : "=f"(y) : "f"(x));
    return y;
}
__device__ __forceinline__ uint32_t packbf(float lo, float hi) {
    uint32_t r; asm("cvt.rn.bf16x2.f32 %0, %1, %2;" : "=r"(r) : "f"(hi), "f"(lo));
    return r;
}
__device__ __forceinline__ float bfhi(float x) {
    return __bfloat162float(__float2bfloat16_rn(x));
}
__device__ __forceinline__ void mma8(float d[4], const uint32_t a[4],
                                     uint32_t b0, uint32_t b1) {
    asm volatile(
        "mma.sync.aligned.m16n8k8.row.col.f32.tf32.tf32.f32 "
        "{%0,%1,%2,%3}, {%4,%5,%6,%7}, {%8,%9}, {%0,%1,%2,%3};"
        : "+f"(d[0]), "+f"(d[1]), "+f"(d[2]), "+f"(d[3])
        : "r"(a[0]), "r"(a[1]), "r"(a[2]), "r"(a[3]), "r"(b0), "r"(b1));
}
__device__ __forceinline__ void mma16bf(float d[4], const uint32_t a[4],
                                        uint32_t b0, uint32_t b1) {
    asm volatile(
        "mma.sync.aligned.m16n8k16.row.col.f32.bf16.bf16.f32 "
        "{%0,%1,%2,%3}, {%4,%5,%6,%7}, {%8,%9}, {%0,%1,%2,%3};"
        : "+f"(d[0]), "+f"(d[1]), "+f"(d[2]), "+f"(d[3])
        : "r"(a[0]), "r"(a[1]), "r"(a[2]), "r"(a[3]), "r"(b0), "r"(b1));
}
__device__ __forceinline__ uint32_t smem_u32(const void* p) {
    uint32_t a;
    asm("{ .reg .u64 t; cvta.to.shared.u64 t, %1; cvt.u32.u64 %0, t; }" : "=r"(a) : "l"(p));
    return a;
}
__device__ __forceinline__ void cpa16(uint32_t s, const void* g) {
    asm volatile("cp.async.ca.shared.global [%0], [%1], 16;" :: "r"(s), "l"(g));
}
#define CPA_COMMIT() asm volatile("cp.async.commit_group;" ::: "memory")
#define CPA_WAIT(n)  asm volatile("cp.async.wait_group %0;" :: "n"(n) : "memory")

// ---------------------------------------------------------------- prep
// Round hs and the three W matrices to tf32 once.
__global__ __launch_bounds__(256) void prep_kernel(
    const float* __restrict__ hs, const float* __restrict__ Wq,
    const float* __restrict__ Wk, const float* __restrict__ Wv)
{
    const size_t i = ((size_t)blockIdx.x * 256 + threadIdx.x) * 4;
    {
        float4 v = *(const float4*)(hs + i);
        *(float4*)(g_hs + i) =
            make_float4(tf32f(v.x), tf32f(v.y), tf32f(v.z), tf32f(v.w));
    }
    if (i < (size_t)HIDDEN * HIDDEN) {
        float4 a = *(const float4*)(Wq + i);
        *(float4*)(g_w[0] + i) =
            make_float4(tf32f(a.x), tf32f(a.y), tf32f(a.z), tf32f(a.w));
        float4 b = *(const float4*)(Wk + i);
        *(float4*)(g_w[1] + i) =
            make_float4(tf32f(b.x), tf32f(b.y), tf32f(b.z), tf32f(b.w));
        float4 c = *(const float4*)(Wv + i);
        *(float4*)(g_w[2] + i) =
            make_float4(tf32f(c.x), tf32f(c.y), tf32f(c.z), tf32f(c.w));
    }
}

// ---------------------------------------------------------------- QKV GEMM
// CTA tile 256x128, BK=32, cp.async double-buffered; inputs pre-rounded.
#define QKV_BUFW  (256 * 36 + 32 * 136)
#define QKV_SMEM  (2 * QKV_BUFW * 4)

__global__ __launch_bounds__(256, 1) void qkv_kernel(
    const float* __restrict__ bq, const float* __restrict__ bk,
    const float* __restrict__ bv)
{
    extern __shared__ float smq[];
    const uint32_t sbase = smem_u32(smq);

    const int z = blockIdx.z;
    const float* W    = g_w[z];
    const float* bias = (z == 0) ? bq : (z == 1) ? bk : bv;

    const int tid = threadIdx.x;
    const int lane = tid & 31, wid = tid >> 5;
    const int wm = wid >> 1, wn = wid & 1;
    const int c0 = blockIdx.x * 128;
    const int t0 = blockIdx.y * 256;
    const int r = lane >> 2, cq = lane & 3;

    float acc[4][8][4];
#pragma unroll
    for (int i = 0; i < 4; i++)
#pragma unroll
        for (int j = 0; j < 8; j++)
#pragma unroll
            for (int k = 0; k < 4; k++) acc[i][j][k] = 0.f;

    auto issue = [&](int t, int b) {
        const uint32_t ab = sbase + (uint32_t)b * QKV_BUFW * 4;
        const uint32_t bb = ab + 256 * 36 * 4;
#pragma unroll
        for (int j = 0; j < 8; j++) {
            int idx = tid + j * 256;
            int row = idx >> 3, c4 = (idx & 7) * 4;
            cpa16(ab + (row * 36 + c4) * 4,
                  g_hs + (size_t)(t0 + row) * HIDDEN + t * 32 + c4);
        }
#pragma unroll
        for (int j = 0; j < 4; j++) {
            int idx = tid + j * 256;
            int row = idx >> 5, c4 = (idx & 31) * 4;
            cpa16(bb + (row * 136 + c4) * 4,
                  W + (size_t)(t * 32 + row) * HIDDEN + c0 + c4);
        }
        CPA_COMMIT();
    };

    issue(0, 0);
    for (int t = 0; t < 32; t++) {
        const int b = t & 1;
        if (t < 31) { issue(t + 1, 1 - b); CPA_WAIT(1); }
        else        { CPA_WAIT(0); }
        __syncthreads();

        const float* A = smq + b * QKV_BUFW;
        const float* B = A + 256 * 36;
#pragma unroll
        for (int ks = 0; ks < 4; ks++) {
            const int kk = ks * 8;
            uint32_t af[4][4], bf[8][2];
#pragma unroll
            for (int mt = 0; mt < 4; mt++) {
                int m = wm * 64 + mt * 16 + r;
                af[mt][0] = __float_as_uint(A[m * 36 + kk + cq]);
                af[mt][1] = __float_as_uint(A[(m + 8) * 36 + kk + cq]);
                af[mt][2] = __float_as_uint(A[m * 36 + kk + cq + 4]);
                af[mt][3] = __float_as_uint(A[(m + 8) * 36 + kk + cq + 4]);
            }
#pragma unroll
            for (int nf = 0; nf < 8; nf++) {
                int nn = wn * 64 + nf * 8 + r;
                bf[nf][0] = __float_as_uint(B[(kk + cq) * 136 + nn]);
                bf[nf][1] = __float_as_uint(B[(kk + cq + 4) * 136 + nn]);
            }
#pragma unroll
            for (int mt = 0; mt < 4; mt++)
#pragma unroll
                for (int nf = 0; nf < 8; nf++)
                    mma8(acc[mt][nf], af[mt], bf[nf][0], bf[nf][1]);
        }
        __syncthreads();
    }

    // Epilogue: bias; Q -> [n][s][d] f32 tf32, K -> [n][d][s] f32 tf32,
    // V -> split bf16 hi/lo [n][d][s].
    const int c2 = cq * 2;
#pragma unroll
    for (int mt = 0; mt < 4; mt++) {
#pragma unroll
        for (int hf = 0; hf < 2; hf++) {
            int t = t0 + wm * 64 + mt * 16 + hf * 8 + r;
            int s = t >> 1, bb = t & 1;
#pragma unroll
            for (int nf = 0; nf < 8; nf++) {
                int cc = c0 + wn * 64 + nf * 8 + c2;
                int h = cc >> 6, d = cc & 63;
                int nH = bb * NHEAD + h;
                float a0 = acc[mt][nf][hf * 2 + 0] + bias[cc];
                float a1 = acc[mt][nf][hf * 2 + 1] + bias[cc + 1];
                if (z == 0) {
                    *(float2*)(g_q + ((size_t)nH * SEQ + s) * HDIM + d) =
                        make_float2(tf32f(a0), tf32f(a1));
                } else if (z == 1) {
                    g_k[((size_t)nH * HDIM + d) * SEQ + s]     = tf32f(a0);
                    g_k[((size_t)nH * HDIM + d + 1) * SEQ + s] = tf32f(a1);
                } else {
                    size_t i0 = ((size_t)nH * HDIM + d) * SEQ + s;
                    size_t i1 = i0 + SEQ;
                    float h0 = bfhi(a0), h1 = bfhi(a1);
                    g_vh[i0] = __float2bfloat16_rn(h0);
                    g_vh[i1] = __float2bfloat16_rn(h1);
                    g_vl[i0] = __float2bfloat16_rn(a0 - h0);
                    g_vl[i1] = __float2bfloat16_rn(a1 - h1);
                }
            }
        }
    }
}

// ---------------------------------------------------------------- attention
// CTA = 256 threads (8 warps), q-tile 128, k-tile 64. Warp w owns q rows
// [16w,16w+16) x all 64 k-cols; P stays in registers (split-bf16 PV:
// PhVh + PhVl + PlVh). K/Vh/Vl double-buffered via cp.async; mask
// prefetched to registers before mma1.
#define AK_ST 72                       // Ks stride (fp32 words)
#define AV_ST 136                      // Vh/Vl stride (bf16 elems)
#define SZ_K  (64 * AK_ST * 4)         // 18432 B per stage
#define SZ_V  (64 * AV_ST * 2)         // 17408 B per stage
#define OFF_VH (2 * SZ_K)
#define OFF_VL (OFF_VH + 2 * SZ_V)
#define ATTN_SMEM (OFF_VL + 2 * SZ_V)  // 106496 B

__global__ __launch_bounds__(256, 1) void attn_kernel(
    const float* __restrict__ mask, float* __restrict__ out)
{
    extern __shared__ char sma[];
    const uint32_t sb = smem_u32(sma);
    float* KsB = (float*)sma;
    __nv_bfloat16* VhB = (__nv_bfloat16*)(sma + OFF_VH);
    __nv_bfloat16* VlB = (__nv_bfloat16*)(sma + OFF_VL);

    const int n  = blockIdx.x;          // head-instance (b*16+h)
    const int q0 = blockIdx.y * 128;
    const int b = n >> 4, h = n & 15;
    const int tid = threadIdx.x;
    const int lane = tid & 31, wid = tid >> 5;
    const int r = lane >> 2, cq = lane & 3;
    const int m = wid * 16 + r;

    const float* qg = g_q + (size_t)n * SEQ * HDIM;
    const float* kg = g_k + (size_t)n * HDIM * SEQ;
    const __nv_bfloat16* vhg = g_vh + (size_t)n * HDIM * SEQ;
    const __nv_bfloat16* vlg = g_vl + (size_t)n * HDIM * SEQ;

    // Q fragments, register-resident (already tf32).
    uint32_t qf[8][4];
#pragma unroll
    for (int kg8 = 0; kg8 < 8; kg8++) {
        const int kk = kg8 * 8;
        qf[kg8][0] = __float_as_uint(qg[(size_t)(q0 + m) * HDIM + kk + cq]);
        qf[kg8][1] = __float_as_uint(qg[(size_t)(q0 + m + 8) * HDIM + kk + cq]);
        qf[kg8][2] = __float_as_uint(qg[(size_t)(q0 + m) * HDIM + kk + cq + 4]);
        qf[kg8][3] = __float_as_uint(qg[(size_t)(q0 + m + 8) * HDIM + kk + cq + 4]);
    }

    float o[8][4];
#pragma unroll
    for (int i = 0; i < 8; i++)
#pragma unroll
        for (int j = 0; j < 4; j++) o[i][j] = 0.f;
    float l0 = 0.f, l1 = 0.f;

    const float C1 = 0.18033688011112042f;   // log2(e)/8
    const float C2 = 1.4426950408889634f;    // log2(e)
    const float* mrow0 = mask + ((size_t)b * SEQ + q0 + m) * SEQ;
    const float* mrow1 = mrow0 + 8 * SEQ;

    auto issueKV = [&](int kt, int st) {
        if (kt >= SEQ / 64) return;
        const int k0 = kt * 64;
        const uint32_t kb = sb + st * SZ_K;
        const uint32_t vh = sb + OFF_VH + st * SZ_V;
        const uint32_t vl = sb + OFF_VL + st * SZ_V;
#pragma unroll
        for (int j = 0; j < 4; j++) {
            int idx = tid + j * 256;
            int row = idx >> 4, c4 = (idx & 15) * 4;
            cpa16(kb + (row * AK_ST + c4) * 4, kg + (size_t)row * SEQ + k0 + c4);
        }
#pragma unroll
        for (int j = 0; j < 2; j++) {
            int idx = tid + j * 256;
            int row = idx >> 3, c8 = (idx & 7) * 8;
            cpa16(vh + row * (AV_ST * 2) + c8 * 2, vhg + (size_t)row * SEQ + k0 + c8);
            cpa16(vl + row * (AV_ST * 2) + c8 * 2, vlg + (size_t)row * SEQ + k0 + c8);
        }
        CPA_COMMIT();
    };

    issueKV(0, 0);
    for (int kt = 0; kt < SEQ / 64; kt++) {
        const int st = kt & 1;
        const int k0 = kt * 64;
        __syncthreads();                 // all warps done with buffer 1-st
        issueKV(kt + 1, 1 - st);

        // mask prefetch (overlaps cp.async wait)
        float2 mk0[8], mk1[8];
#pragma unroll
        for (int nt = 0; nt < 8; nt++) {
            const int col = k0 + nt * 8 + cq * 2;
            mk0[nt] = *(const float2*)(mrow0 + col);
            mk1[nt] = *(const float2*)(mrow1 + col);
        }

        if (kt < SEQ / 64 - 1) { CPA_WAIT(1); } else { CPA_WAIT(0); }
        __syncthreads();

        const float* Ks = KsB + st * (64 * AK_ST);
        const char* VhS = (const char*)VhB + st * SZ_V;
        const char* VlS = (const char*)VlB + st * SZ_V;

        // mma1: S[16][64] = Q . K^T (tf32, d=64)
        float s[8][4];
#pragma unroll
        for (int i = 0; i < 8; i++)
#pragma unroll
            for (int j = 0; j < 4; j++) s[i][j] = 0.f;
#pragma unroll
        for (int kg8 = 0; kg8 < 8; kg8++) {
            const int kk = kg8 * 8;
#pragma unroll
            for (int nt = 0; nt < 8; nt++) {
                int nn = nt * 8 + r;
                uint32_t b0 = __float_as_uint(Ks[(kk + cq) * AK_ST + nn]);
                uint32_t b1 = __float_as_uint(Ks[(kk + cq + 4) * AK_ST + nn]);
                mma8(s[nt], qf[kg8], b0, b1);
            }
        }

        // softmax (max-free) + split-bf16 P fragments
        uint32_t pah[4][4], pal[4][4];
#pragma unroll
        for (int nt = 0; nt < 8; nt++) {
            float p0 = ex2f(s[nt][0] * C1 + mk0[nt].x * C2);
            float p1 = ex2f(s[nt][1] * C1 + mk0[nt].y * C2);
            float p2 = ex2f(s[nt][2] * C1 + mk1[nt].x * C2);
            float p3 = ex2f(s[nt][3] * C1 + mk1[nt].y * C2);
            l0 += p0 + p1;
            l1 += p2 + p3;
            float h0 = bfhi(p0), h1 = bfhi(p1), h2 = bfhi(p2), h3 = bfhi(p3);
            const int g = nt >> 1, o2 = (nt & 1) * 2;
            pah[g][o2 + 0] = packbf(h0, h1);
            pah[g][o2 + 1] = packbf(h2, h3);
            pal[g][o2 + 0] = packbf(p0 - h0, p1 - h1);
            pal[g][o2 + 1] = packbf(p2 - h2, p3 - h3);
        }

        // mma2: O += PhVh + PhVl + PlVh (bf16, k=64)
#pragma unroll
        for (int kg2 = 0; kg2 < 4; kg2++) {
            const int kk = kg2 * 16;
#pragma unroll
            for (int nt = 0; nt < 8; nt++) {
                int dd = nt * 8 + r;
                const char* vrh = VhS + dd * (AV_ST * 2);
                const char* vrl = VlS + dd * (AV_ST * 2);
                uint32_t bh0 = *(const uint32_t*)(vrh + kk * 2 + cq * 4);
                uint32_t bh1 = *(const uint32_t*)(vrh + (kk + 8) * 2 + cq * 4);
                uint32_t bl0 = *(const uint32_t*)(vrl + kk * 2 + cq * 4);
                uint32_t bl1 = *(const uint32_t*)(vrl + (kk + 8) * 2 + cq * 4);
                mma16bf(o[nt], pah[kg2], bh0, bh1);
                mma16bf(o[nt], pah[kg2], bl0, bl1);
                mma16bf(o[nt], pal[kg2], bh0, bh1);
            }
        }
    }

    // Row sums: quad reduce, normalize, store.
    l0 += __shfl_xor_sync(0xffffffffu, l0, 1);
    l0 += __shfl_xor_sync(0xffffffffu, l0, 2);
    l1 += __shfl_xor_sync(0xffffffffu, l1, 1);
    l1 += __shfl_xor_sync(0xffffffffu, l1, 2);
    const float inv0 = 1.0f / l0, inv1 = 1.0f / l1;
    const int qr0 = q0 + m, qr1 = qr0 + 8;
#pragma unroll
    for (int nt = 0; nt < 8; nt++) {
        int dd = nt * 8 + cq * 2;
        *(float2*)(out + ((size_t)qr0 * BATCH + b) * HIDDEN + h * HDIM + dd) =
            make_float2(o[nt][0] * inv0, o[nt][1] * inv0);
        *(float2*)(out + ((size_t)qr1 * BATCH + b) * HIDDEN + h * HDIM + dd) =
            make_float2(o[nt][2] * inv1, o[nt][3] * inv1);
    }
}

// ----------------------------------------------------------------
extern "C" void kernel_launch(void* const* d_in, const int* in_sizes, int n_in,
                              void* d_out, int out_size)
{
    const float* hs   = (const float*)d_in[0];
    const float* mask = (const float*)d_in[1];
    const float* Wq   = (const float*)d_in[2];
    const float* bq   = (const float*)d_in[3];
    const float* Wk   = (const float*)d_in[4];
    const float* bk   = (const float*)d_in[5];
    const float* Wv   = (const float*)d_in[6];
    const float* bv   = (const float*)d_in[7];
    float* out = (float*)d_out;

    cudaFuncSetAttribute(qkv_kernel,
                         cudaFuncAttributeMaxDynamicSharedMemorySize, QKV_SMEM);
    cudaFuncSetAttribute(attn_kernel,
                         cudaFuncAttributeMaxDynamicSharedMemorySize, ATTN_SMEM);

    prep_kernel<<<(TOK * HIDDEN / 4) / 256, 256>>>(hs, Wq, Wk, Wv);

    dim3 g1(HIDDEN / 128, TOK / 256, 3);
    qkv_kernel<<<g1, 256, QKV_SMEM>>>(bq, bk, bv);

    dim3 g2(NH, SEQ / 128);
    attn_kernel<<<g2, 256, ATTN_SMEM>>>(mask, out);
}

// round 7
// speedup vs baseline: 1.8417x; 1.8369x over previous
#include <cuda_runtime.h>
#include <cuda_fp16.h>
#include <cstdint>

#define SEQ     2048
#define BATCH   2
#define HIDDEN  1024
#define NHEAD   16
#define HDIM    64
#define NH      32
#define TOK     4096

// Scratch (device globals).
__device__ __half g_hs[(size_t)TOK * HIDDEN];        // hs, fp16
__device__ __half g_wt[3][HIDDEN * HIDDEN];          // W^T fp16: wt[c][k]
__device__ __half g_q[(size_t)NH * SEQ * HDIM];      // [n][s][d]
__device__ __half g_k[(size_t)NH * SEQ * HDIM];      // [n][s][d]
__device__ __half g_v[(size_t)NH * HDIM * SEQ];      // [n][d][s]

// ---------------------------------------------------------------- helpers
__device__ __forceinline__ float ex2f(float x) {
    float y; asm("ex2.approx.ftz.f32 %0, %1;" : "=f"(y) : "f"(x));
    return y;
}
__device__ __forceinline__ uint32_t packh2(float lo, float hi) {
    __half2 h = __floats2half2_rn(lo, hi);
    return *(uint32_t*)&h;
}
// m16n8k16 fp16: D += A*B (f32 accumulate)
__device__ __forceinline__ void mma16f(float d[4], const uint32_t a[4],
                                       uint32_t b0, uint32_t b1) {
    asm volatile(
        "mma.sync.aligned.m16n8k16.row.col.f32.f16.f16.f32 "
        "{%0,%1,%2,%3}, {%4,%5,%6,%7}, {%8,%9}, {%0,%1,%2,%3};"
        : "+f"(d[0]), "+f"(d[1]), "+f"(d[2]), "+f"(d[3])
        : "r"(a[0]), "r"(a[1]), "r"(a[2]), "r"(a[3]), "r"(b0), "r"(b1));
}
__device__ __forceinline__ uint32_t smem_u32(const void* p) {
    uint32_t a;
    asm("{ .reg .u64 t; cvta.to.shared.u64 t, %1; cvt.u32.u64 %0, t; }" : "=r"(a) : "l"(p));
    return a;
}
__device__ __forceinline__ void cpa16(uint32_t s, const void* g) {
    asm volatile("cp.async.ca.shared.global [%0], [%1], 16;" :: "r"(s), "l"(g));
}
#define CPA_COMMIT() asm volatile("cp.async.commit_group;" ::: "memory")
#define CPA_WAIT(n)  asm volatile("cp.async.wait_group %0;" :: "n"(n) : "memory")

// ---------------------------------------------------------------- prep
__global__ __launch_bounds__(256) void prep_hs(const float* __restrict__ hs) {
    const size_t i = ((size_t)blockIdx.x * 256 + threadIdx.x) * 4;
    float4 v = *(const float4*)(hs + i);
    __half2* d = (__half2*)(g_hs + i);
    d[0] = __floats2half2_rn(v.x, v.y);
    d[1] = __floats2half2_rn(v.z, v.w);
}
// Transpose W[k][c] -> wt[c][k], fp16.
__global__ void prep_w(const float* __restrict__ Wq, const float* __restrict__ Wk,
                       const float* __restrict__ Wv) {
    __shared__ float t[32][33];
    const float* W = (blockIdx.z == 0) ? Wq : (blockIdx.z == 1) ? Wk : Wv;
    __half* wt = g_wt[blockIdx.z];
    const int k0 = blockIdx.y * 32, c0 = blockIdx.x * 32;
    for (int i = threadIdx.y; i < 32; i += 8)
        t[i][threadIdx.x] = W[(size_t)(k0 + i) * HIDDEN + c0 + threadIdx.x];
    __syncthreads();
    for (int i = threadIdx.y; i < 32; i += 8)
        wt[(size_t)(c0 + i) * HIDDEN + k0 + threadIdx.x] =
            __float2half_rn(t[threadIdx.x][i]);
}

// ---------------------------------------------------------------- QKV GEMM
// C[t][c] = sum_k hs[t][k]*W[k][c] + bias[c]. CTA 256x128, BK=64 (fp16),
// cp.async double-buffered. 16 warps: 8(M)x2(N), warp tile 32x64.
// All fp16 smem tiles use row stride 144 B (72 halves): fragment loads at
// addr = row*144 + cq*4 (+16) give banks (row*4 + cq) mod 32 -> conflict-free.
#define QST       144                      // bytes per smem row
#define QKV_A_SZ  (256 * QST)              // 36864
#define QKV_B_SZ  (128 * QST)              // 18432
#define QKV_STG   (QKV_A_SZ + QKV_B_SZ)    // 55296
#define QKV_SMEM  (2 * QKV_STG)            // 110592

__global__ __launch_bounds__(512, 1) void qkv_kernel(
    const float* __restrict__ bq, const float* __restrict__ bk,
    const float* __restrict__ bv)
{
    extern __shared__ char smq[];
    const uint32_t sbase = smem_u32(smq);

    const int z = blockIdx.z;
    const __half* W   = g_wt[z];
    const float* bias = (z == 0) ? bq : (z == 1) ? bk : bv;

    const int tid = threadIdx.x;
    const int lane = tid & 31, wid = tid >> 5;
    const int wm = wid >> 1, wn = wid & 1;       // 8 x 2
    const int c0 = blockIdx.x * 128;
    const int t0 = blockIdx.y * 256;
    const int r = lane >> 2, cq = lane & 3;

    float acc[2][8][4];
#pragma unroll
    for (int i = 0; i < 2; i++)
#pragma unroll
        for (int j = 0; j < 8; j++)
#pragma unroll
            for (int k = 0; k < 4; k++) acc[i][j][k] = 0.f;

    auto issue = [&](int t, int st) {
        const uint32_t ab = sbase + (uint32_t)st * QKV_STG;
        const uint32_t bb = ab + QKV_A_SZ;
#pragma unroll
        for (int j = 0; j < 4; j++) {            // A: 2048 chunks / 512 thr
            int idx = tid + j * 512;
            int row = idx >> 3, c = idx & 7;
            cpa16(ab + row * QST + c * 16,
                  g_hs + (size_t)(t0 + row) * HIDDEN + t * 64 + c * 8);
        }
#pragma unroll
        for (int j = 0; j < 2; j++) {            // B: 1024 chunks
            int idx = tid + j * 512;
            int row = idx >> 3, c = idx & 7;
            cpa16(bb + row * QST + c * 16,
                  W + (size_t)(c0 + row) * HIDDEN + t * 64 + c * 8);
        }
        CPA_COMMIT();
    };

    issue(0, 0);
    for (int t = 0; t < 16; t++) {
        const int st = t & 1;
        if (t < 15) { issue(t + 1, 1 - st); CPA_WAIT(1); }
        else        { CPA_WAIT(0); }
        __syncthreads();

        const char* A = smq + st * QKV_STG;
        const char* B = A + QKV_A_SZ;
#pragma unroll
        for (int ks = 0; ks < 4; ks++) {
            const int kb = ks * 32;              // byte offset of k16 step
            uint32_t af[2][4], bf[8][2];
#pragma unroll
            for (int mt = 0; mt < 2; mt++) {
                int m = wm * 32 + mt * 16 + r;
                af[mt][0] = *(const uint32_t*)(A + m * QST + kb + cq * 4);
                af[mt][1] = *(const uint32_t*)(A + (m + 8) * QST + kb + cq * 4);
                af[mt][2] = *(const uint32_t*)(A + m * QST + kb + cq * 4 + 16);
                af[mt][3] = *(const uint32_t*)(A + (m + 8) * QST + kb + cq * 4 + 16);
            }
#pragma unroll
            for (int nf = 0; nf < 8; nf++) {
                int nn = wn * 64 + nf * 8 + r;
                bf[nf][0] = *(const uint32_t*)(B + nn * QST + kb + cq * 4);
                bf[nf][1] = *(const uint32_t*)(B + nn * QST + kb + cq * 4 + 16);
            }
#pragma unroll
            for (int mt = 0; mt < 2; mt++)
#pragma unroll
                for (int nf = 0; nf < 8; nf++)
                    mma16f(acc[mt][nf], af[mt], bf[nf][0], bf[nf][1]);
        }
        __syncthreads();
    }

    // Epilogue: +bias, convert fp16, scatter: Q,K -> [n][s][d]; V -> [n][d][s].
    const int c2 = cq * 2;
#pragma unroll
    for (int mt = 0; mt < 2; mt++) {
#pragma unroll
        for (int hf = 0; hf < 2; hf++) {
            int t = t0 + wm * 32 + mt * 16 + hf * 8 + r;
            int s = t >> 1, bb = t & 1;
#pragma unroll
            for (int nf = 0; nf < 8; nf++) {
                int cc = c0 + wn * 64 + nf * 8 + c2;
                int h = cc >> 6, d = cc & 63;
                int nH = bb * NHEAD + h;
                float a0 = acc[mt][nf][hf * 2 + 0] + bias[cc];
                float a1 = acc[mt][nf][hf * 2 + 1] + bias[cc + 1];
                if (z == 2) {
                    g_v[((size_t)nH * HDIM + d) * SEQ + s]     = __float2half_rn(a0);
                    g_v[((size_t)nH * HDIM + d + 1) * SEQ + s] = __float2half_rn(a1);
                } else {
                    __half* dst = (z == 0) ? g_q : g_k;
                    *(__half2*)(dst + ((size_t)nH * SEQ + s) * HDIM + d) =
                        __floats2half2_rn(a0, a1);
                }
            }
        }
    }
}

// ---------------------------------------------------------------- attention
// CTA = 256 threads (8 warps), q-tile 128, k-tile 64, 2 CTAs/SM.
// Warp w owns q rows [16w,16w+16) x all 64 keys; P stays in registers as
// fp16 A-fragments (S accum layout == A fragment layout). Max-free softmax.
// K staged [s][d], V staged [d][s], both fp16 stride 144 B, double-buffered.
#define AST   144
#define A_KSZ (64 * AST)                  // 9216 B per stage
#define ATTN_SMEM (4 * A_KSZ)             // K x2 stages + V x2 = 36864 B

__global__ __launch_bounds__(256, 2) void attn_kernel(
    const float* __restrict__ mask, float* __restrict__ out)
{
    __shared__ __align__(16) char sma[ATTN_SMEM];
    const uint32_t sb = smem_u32(sma);

    const int n  = blockIdx.x;            // head-instance (b*16+h)
    const int q0 = blockIdx.y * 128;
    const int b = n >> 4, h = n & 15;
    const int tid = threadIdx.x;
    const int lane = tid & 31, wid = tid >> 5;
    const int r = lane >> 2, cq = lane & 3;
    const int m = wid * 16 + r;

    const __half* qg = g_q + (size_t)n * SEQ * HDIM;
    const __half* kg = g_k + (size_t)n * SEQ * HDIM;
    const __half* vg = g_v + (size_t)n * HDIM * SEQ;

    // Q fragments, register-resident: 4 k16-steps over d=64.
    uint32_t qf[4][4];
#pragma unroll
    for (int ks = 0; ks < 4; ks++) {
        const int dk = ks * 16 + cq * 2;
        qf[ks][0] = *(const uint32_t*)(qg + (size_t)(q0 + m) * HDIM + dk);
        qf[ks][1] = *(const uint32_t*)(qg + (size_t)(q0 + m + 8) * HDIM + dk);
        qf[ks][2] = *(const uint32_t*)(qg + (size_t)(q0 + m) * HDIM + dk + 8);
        qf[ks][3] = *(const uint32_t*)(qg + (size_t)(q0 + m + 8) * HDIM + dk + 8);
    }

    float o[8][4];
#pragma unroll
    for (int i = 0; i < 8; i++)
#pragma unroll
        for (int j = 0; j < 4; j++) o[i][j] = 0.f;
    float l0 = 0.f, l1 = 0.f;

    const float C1 = 0.18033688011112042f;   // log2(e)/8
    const float C2 = 1.4426950408889634f;    // log2(e)
    const float* mrow0 = mask + ((size_t)b * SEQ + q0 + m) * SEQ;
    const float* mrow1 = mrow0 + 8 * SEQ;

    auto issueKV = [&](int kt, int st) {
        if (kt >= SEQ / 64) return;
        const int k0 = kt * 64;
        const uint32_t kb = sb + st * A_KSZ;
        const uint32_t vb = sb + 2 * A_KSZ + st * A_KSZ;
#pragma unroll
        for (int j = 0; j < 2; j++) {         // K: 512 chunks / 256 thr
            int idx = tid + j * 256;
            int row = idx >> 3, c = idx & 7;
            cpa16(kb + row * AST + c * 16,
                  kg + (size_t)(k0 + row) * HDIM + c * 8);
        }
#pragma unroll
        for (int j = 0; j < 2; j++) {         // V: 512 chunks
            int idx = tid + j * 256;
            int row = idx >> 3, c = idx & 7;
            cpa16(vb + row * AST + c * 16,
                  vg + (size_t)row * SEQ + k0 + c * 8);
        }
        CPA_COMMIT();
    };

    issueKV(0, 0);
    for (int kt = 0; kt < SEQ / 64; kt++) {
        const int st = kt & 1;
        const int k0 = kt * 64;
        __syncthreads();                      // done consuming buffer 1-st
        issueKV(kt + 1, 1 - st);
        if (kt < SEQ / 64 - 1) { CPA_WAIT(1); } else { CPA_WAIT(0); }
        __syncthreads();

        const char* Ks = sma + st * A_KSZ;
        const char* Vs = sma + 2 * A_KSZ + st * A_KSZ;

        // mma1: S[16][64] = Q . K^T  (fp16, d=64 -> 4 k16 steps)
        float s[8][4];
#pragma unroll
        for (int i = 0; i < 8; i++)
#pragma unroll
            for (int j = 0; j < 4; j++) s[i][j] = 0.f;
#pragma unroll
        for (int ks = 0; ks < 4; ks++) {
            const int kb = ks * 32;
#pragma unroll
            for (int nt = 0; nt < 8; nt++) {
                int nn = nt * 8 + r;
                uint32_t b0 = *(const uint32_t*)(Ks + nn * AST + kb + cq * 4);
                uint32_t b1 = *(const uint32_t*)(Ks + nn * AST + kb + cq * 4 + 16);
                mma16f(s[nt], qf[ks], b0, b1);
            }
        }

        // softmax (max-free): p = exp2(S*C1 + mask*C2); pack fp16 A-frags
        uint32_t pa[4][4];
#pragma unroll
        for (int nt = 0; nt < 8; nt++) {
            const int col = k0 + nt * 8 + cq * 2;
            float2 mk0 = *(const float2*)(mrow0 + col);
            float2 mk1 = *(const float2*)(mrow1 + col);
            float p0 = ex2f(s[nt][0] * C1 + mk0.x * C2);
            float p1 = ex2f(s[nt][1] * C1 + mk0.y * C2);
            float p2 = ex2f(s[nt][2] * C1 + mk1.x * C2);
            float p3 = ex2f(s[nt][3] * C1 + mk1.y * C2);
            l0 += p0 + p1;
            l1 += p2 + p3;
            const int g = nt >> 1, o2 = (nt & 1) * 2;
            pa[g][o2 + 0] = packh2(p0, p1);
            pa[g][o2 + 1] = packh2(p2, p3);
        }

        // mma2: O[16][64] += P . V  (fp16, k=64 -> 4 k16 steps)
#pragma unroll
        for (int kg2 = 0; kg2 < 4; kg2++) {
            const int kb = kg2 * 32;
#pragma unroll
            for (int nt = 0; nt < 8; nt++) {
                int dd = nt * 8 + r;
                uint32_t b0 = *(const uint32_t*)(Vs + dd * AST + kb + cq * 4);
                uint32_t b1 = *(const uint32_t*)(Vs + dd * AST + kb + cq * 4 + 16);
                mma16f(o[nt], pa[kg2], b0, b1);
            }
        }
    }

    // Row sums: quad reduce, normalize, store fp32.
    l0 += __shfl_xor_sync(0xffffffffu, l0, 1);
    l0 += __shfl_xor_sync(0xffffffffu, l0, 2);
    l1 += __shfl_xor_sync(0xffffffffu, l1, 1);
    l1 += __shfl_xor_sync(0xffffffffu, l1, 2);
    const float inv0 = 1.0f / l0, inv1 = 1.0f / l1;
    const int qr0 = q0 + m, qr1 = qr0 + 8;
#pragma unroll
    for (int nt = 0; nt < 8; nt++) {
        int dd = nt * 8 + cq * 2;
        *(float2*)(out + ((size_t)qr0 * BATCH + b) * HIDDEN + h * HDIM + dd) =
            make_float2(o[nt][0] * inv0, o[nt][1] * inv0);
        *(float2*)(out + ((size_t)qr1 * BATCH + b) * HIDDEN + h * HDIM + dd) =
            make_float2(o[nt][2] * inv1, o[nt][3] * inv1);
    }
}

// ----------------------------------------------------------------
extern "C" void kernel_launch(void* const* d_in, const int* in_sizes, int n_in,
                              void* d_out, int out_size)
{
    const float* hs   = (const float*)d_in[0];
    const float* mask = (const float*)d_in[1];
    const float* Wq   = (const float*)d_in[2];
    const float* bq   = (const float*)d_in[3];
    const float* Wk   = (const float*)d_in[4];
    const float* bk   = (const float*)d_in[5];
    const float* Wv   = (const float*)d_in[6];
    const float* bv   = (const float*)d_in[7];
    float* out = (float*)d_out;

    cudaFuncSetAttribute(qkv_kernel,
                         cudaFuncAttributeMaxDynamicSharedMemorySize, QKV_SMEM);

    prep_hs<<<(TOK * HIDDEN / 4) / 256, 256>>>(hs);
    prep_w<<<dim3(HIDDEN / 32, HIDDEN / 32, 3), dim3(32, 8)>>>(Wq, Wk, Wv);

    dim3 g1(HIDDEN / 128, TOK / 256, 3);
    qkv_kernel<<<g1, 512, QKV_SMEM>>>(bq, bk, bv);

    dim3 g2(NH, SEQ / 128);
    attn_kernel<<<g2, 256>>>(mask, out);
}

// round 8
// speedup vs baseline: 2.0986x; 1.1395x over previous
#include <cuda_runtime.h>
#include <cuda_fp16.h>
#include <cstdint>

#define SEQ     2048
#define BATCH   2
#define HIDDEN  1024
#define NHEAD   16
#define HDIM    64
#define NH      32
#define TOK     4096

// Scratch (device globals).
__device__ __half g_hs[(size_t)TOK * HIDDEN];        // hs, fp16
__device__ __half g_wt[3][HIDDEN * HIDDEN];          // W^T fp16: wt[c][k]
__device__ __half g_q[(size_t)NH * SEQ * HDIM];      // [n][s][d]
__device__ __half g_k[(size_t)NH * SEQ * HDIM];      // [n][s][d]
__device__ __half g_v[(size_t)NH * HDIM * SEQ];      // [n][d][s]

// ---------------------------------------------------------------- helpers
__device__ __forceinline__ float ex2f(float x) {
    float y; asm("ex2.approx.ftz.f32 %0, %1;" : "=f"(y) : "f"(x));
    return y;
}
__device__ __forceinline__ uint32_t packh2(float lo, float hi) {
    __half2 h = __floats2half2_rn(lo, hi);
    return *(uint32_t*)&h;
}
__device__ __forceinline__ void mma16f(float d[4], const uint32_t a[4],
                                       uint32_t b0, uint32_t b1) {
    asm volatile(
        "mma.sync.aligned.m16n8k16.row.col.f32.f16.f16.f32 "
        "{%0,%1,%2,%3}, {%4,%5,%6,%7}, {%8,%9}, {%0,%1,%2,%3};"
        : "+f"(d[0]), "+f"(d[1]), "+f"(d[2]), "+f"(d[3])
        : "r"(a[0]), "r"(a[1]), "r"(a[2]), "r"(a[3]), "r"(b0), "r"(b1));
}
__device__ __forceinline__ void ldsm4(uint32_t r[4], uint32_t addr) {
    asm volatile("ldmatrix.sync.aligned.m8n8.x4.shared.b16 {%0,%1,%2,%3}, [%4];"
        : "=r"(r[0]), "=r"(r[1]), "=r"(r[2]), "=r"(r[3]) : "r"(addr));
}
__device__ __forceinline__ uint32_t smem_u32(const void* p) {
    uint32_t a;
    asm("{ .reg .u64 t; cvta.to.shared.u64 t, %1; cvt.u32.u64 %0, t; }" : "=r"(a) : "l"(p));
    return a;
}
__device__ __forceinline__ void cpa16(uint32_t s, const void* g) {
    asm volatile("cp.async.ca.shared.global [%0], [%1], 16;" :: "r"(s), "l"(g));
}
#define CPA_COMMIT() asm volatile("cp.async.commit_group;" ::: "memory")
#define CPA_WAIT(n)  asm volatile("cp.async.wait_group %0;" :: "n"(n) : "memory")

// ---------------------------------------------------------------- prep
__global__ __launch_bounds__(256) void prep_hs(const float* __restrict__ hs) {
    const size_t i = ((size_t)blockIdx.x * 256 + threadIdx.x) * 4;
    float4 v = *(const float4*)(hs + i);
    __half2* d = (__half2*)(g_hs + i);
    d[0] = __floats2half2_rn(v.x, v.y);
    d[1] = __floats2half2_rn(v.z, v.w);
}
__global__ void prep_w(const float* __restrict__ Wq, const float* __restrict__ Wk,
                       const float* __restrict__ Wv) {
    __shared__ float t[32][33];
    const float* W = (blockIdx.z == 0) ? Wq : (blockIdx.z == 1) ? Wk : Wv;
    __half* wt = g_wt[blockIdx.z];
    const int k0 = blockIdx.y * 32, c0 = blockIdx.x * 32;
    for (int i = threadIdx.y; i < 32; i += 8)
        t[i][threadIdx.x] = W[(size_t)(k0 + i) * HIDDEN + c0 + threadIdx.x];
    __syncthreads();
    for (int i = threadIdx.y; i < 32; i += 8)
        wt[(size_t)(c0 + i) * HIDDEN + k0 + threadIdx.x] =
            __float2half_rn(t[threadIdx.x][i]);
}

// ---------------------------------------------------------------- QKV GEMM
// CTA 256x128, BK=64 fp16, cp.async double-buffered, ldmatrix fragments.
// 16 warps: 8(M)x2(N), warp tile 32x64. Rows stride 144 B: conflict-free.
#define QST       144
#define QKV_A_SZ  (256 * QST)
#define QKV_B_SZ  (128 * QST)
#define QKV_STG   (QKV_A_SZ + QKV_B_SZ)
#define QKV_SMEM  (2 * QKV_STG)

__global__ __launch_bounds__(512, 1) void qkv_kernel(
    const float* __restrict__ bq, const float* __restrict__ bk,
    const float* __restrict__ bv)
{
    extern __shared__ char smq[];
    const uint32_t sbase = smem_u32(smq);

    const int z = blockIdx.z;
    const __half* W   = g_wt[z];
    const float* bias = (z == 0) ? bq : (z == 1) ? bk : bv;

    const int tid = threadIdx.x;
    const int lane = tid & 31, wid = tid >> 5;
    const int wm = wid >> 1, wn = wid & 1;       // 8 x 2
    const int c0 = blockIdx.x * 128;
    const int t0 = blockIdx.y * 256;
    const int r = lane >> 2, cq = lane & 3;
    // ldmatrix lane->address maps
    const int larow = lane & 15;                 // A frags
    const int lakof = (lane >> 4) << 4;
    const int lbrow = ((lane & 16) >> 1) | (lane & 7);   // B frags
    const int lbkof = (lane & 8) << 1;

    float acc[2][8][4];
#pragma unroll
    for (int i = 0; i < 2; i++)
#pragma unroll
        for (int j = 0; j < 8; j++)
#pragma unroll
            for (int k = 0; k < 4; k++) acc[i][j][k] = 0.f;

    auto issue = [&](int t, int st) {
        const uint32_t ab = sbase + (uint32_t)st * QKV_STG;
        const uint32_t bb = ab + QKV_A_SZ;
#pragma unroll
        for (int j = 0; j < 4; j++) {
            int idx = tid + j * 512;
            int row = idx >> 3, c = idx & 7;
            cpa16(ab + row * QST + c * 16,
                  g_hs + (size_t)(t0 + row) * HIDDEN + t * 64 + c * 8);
        }
#pragma unroll
        for (int j = 0; j < 2; j++) {
            int idx = tid + j * 512;
            int row = idx >> 3, c = idx & 7;
            cpa16(bb + row * QST + c * 16,
                  W + (size_t)(c0 + row) * HIDDEN + t * 64 + c * 8);
        }
        CPA_COMMIT();
    };

    issue(0, 0);
    for (int t = 0; t < 16; t++) {
        const int st = t & 1;
        if (t < 15) { issue(t + 1, 1 - st); CPA_WAIT(1); }
        else        { CPA_WAIT(0); }
        __syncthreads();

        const uint32_t aB = sbase + st * QKV_STG;
        const uint32_t bB = aB + QKV_A_SZ;
#pragma unroll
        for (int ks = 0; ks < 4; ks++) {
            const int kb = ks * 32;
            uint32_t af[2][4], bf[4][4];
#pragma unroll
            for (int mt = 0; mt < 2; mt++)
                ldsm4(af[mt], aB + (wm * 32 + mt * 16 + larow) * QST + kb + lakof);
#pragma unroll
            for (int g = 0; g < 4; g++)
                ldsm4(bf[g], bB + (wn * 64 + g * 16 + lbrow) * QST + kb + lbkof);
#pragma unroll
            for (int mt = 0; mt < 2; mt++)
#pragma unroll
                for (int g = 0; g < 4; g++) {
                    mma16f(acc[mt][2 * g],     af[mt], bf[g][0], bf[g][1]);
                    mma16f(acc[mt][2 * g + 1], af[mt], bf[g][2], bf[g][3]);
                }
        }
        __syncthreads();
    }

    // Epilogue: +bias, fp16, scatter: Q,K -> [n][s][d]; V -> [n][d][s].
    const int c2 = cq * 2;
#pragma unroll
    for (int mt = 0; mt < 2; mt++) {
#pragma unroll
        for (int hf = 0; hf < 2; hf++) {
            int t = t0 + wm * 32 + mt * 16 + hf * 8 + r;
            int s = t >> 1, bb = t & 1;
#pragma unroll
            for (int nf = 0; nf < 8; nf++) {
                int cc = c0 + wn * 64 + nf * 8 + c2;
                int h = cc >> 6, d = cc & 63;
                int nH = bb * NHEAD + h;
                float a0 = acc[mt][nf][hf * 2 + 0] + bias[cc];
                float a1 = acc[mt][nf][hf * 2 + 1] + bias[cc + 1];
                if (z == 2) {
                    g_v[((size_t)nH * HDIM + d) * SEQ + s]     = __float2half_rn(a0);
                    g_v[((size_t)nH * HDIM + d + 1) * SEQ + s] = __float2half_rn(a1);
                } else {
                    __half* dst = (z == 0) ? g_q : g_k;
                    *(__half2*)(dst + ((size_t)nH * SEQ + s) * HDIM + d) =
                        __floats2half2_rn(a0, a1);
                }
            }
        }
    }
}

// ---------------------------------------------------------------- attention
// CTA = 256 threads (8 warps), q-tile 128, k-tile 64, 2 CTAs/SM.
// Warp w owns q rows [16w,16w+16) x all 64 keys; P register-resident fp16.
// 3-stage cp.async pipeline, ONE barrier per ktile; ldmatrix fragments.
#define AST   144
#define A_STG (64 * AST)                  // 9216 B per stage (K or V)
#define ATTN_SMEM (6 * A_STG)             // 3 K stages + 3 V stages = 55296

__global__ __launch_bounds__(256, 2) void attn_kernel(
    const float* __restrict__ mask, float* __restrict__ out)
{
    extern __shared__ char sma[];
    const uint32_t sb = smem_u32(sma);

    const int n  = blockIdx.x;            // head-instance (b*16+h)
    const int q0 = blockIdx.y * 128;
    const int b = n >> 4, h = n & 15;
    const int tid = threadIdx.x;
    const int lane = tid & 31, wid = tid >> 5;
    const int r = lane >> 2, cq = lane & 3;
    const int m = wid * 16 + r;
    const int lbrow = ((lane & 16) >> 1) | (lane & 7);   // B-frag ldmatrix map
    const int lbkof = (lane & 8) << 1;

    const __half* qg = g_q + (size_t)n * SEQ * HDIM;
    const __half* kg = g_k + (size_t)n * SEQ * HDIM;
    const __half* vg = g_v + (size_t)n * HDIM * SEQ;

    // Q fragments, register-resident: 4 k16-steps over d=64.
    uint32_t qf[4][4];
#pragma unroll
    for (int ks = 0; ks < 4; ks++) {
        const int dk = ks * 16 + cq * 2;
        qf[ks][0] = *(const uint32_t*)(qg + (size_t)(q0 + m) * HDIM + dk);
        qf[ks][1] = *(const uint32_t*)(qg + (size_t)(q0 + m + 8) * HDIM + dk);
        qf[ks][2] = *(const uint32_t*)(qg + (size_t)(q0 + m) * HDIM + dk + 8);
        qf[ks][3] = *(const uint32_t*)(qg + (size_t)(q0 + m + 8) * HDIM + dk + 8);
    }

    float o[8][4];
#pragma unroll
    for (int i = 0; i < 8; i++)
#pragma unroll
        for (int j = 0; j < 4; j++) o[i][j] = 0.f;
    float l0 = 0.f, l1 = 0.f;

    const float C1 = 0.18033688011112042f;   // log2(e)/8
    const float C2 = 1.4426950408889634f;    // log2(e)
    const float* mrow0 = mask + ((size_t)b * SEQ + q0 + m) * SEQ;
    const float* mrow1 = mrow0 + 8 * SEQ;

    auto issueKV = [&](int kt) {
        if (kt >= SEQ / 64) return;
        const int st = kt % 3;
        const int k0 = kt * 64;
        const uint32_t kb = sb + st * A_STG;
        const uint32_t vb = sb + 3 * A_STG + st * A_STG;
#pragma unroll
        for (int j = 0; j < 2; j++) {
            int idx = tid + j * 256;
            int row = idx >> 3, c = idx & 7;
            cpa16(kb + row * AST + c * 16,
                  kg + (size_t)(k0 + row) * HDIM + c * 8);
        }
#pragma unroll
        for (int j = 0; j < 2; j++) {
            int idx = tid + j * 256;
            int row = idx >> 3, c = idx & 7;
            cpa16(vb + row * AST + c * 16,
                  vg + (size_t)row * SEQ + k0 + c * 8);
        }
        CPA_COMMIT();
    };

    issueKV(0);
    issueKV(1);
    for (int kt = 0; kt < SEQ / 64; kt++) {
        const int st = kt % 3;
        const int k0 = kt * 64;
        if (kt < SEQ / 64 - 1) { CPA_WAIT(1); } else { CPA_WAIT(0); }
        __syncthreads();                 // stage kt visible; stage kt-1 consumed
        issueKV(kt + 2);

        const uint32_t Ks = sb + st * A_STG;
        const uint32_t Vs = sb + 3 * A_STG + st * A_STG;

        // mma1: S[16][64] = Q . K^T  (fp16, 4 k16 steps, ldmatrix B)
        float s[8][4];
#pragma unroll
        for (int i = 0; i < 8; i++)
#pragma unroll
            for (int j = 0; j < 4; j++) s[i][j] = 0.f;
#pragma unroll
        for (int ks = 0; ks < 4; ks++) {
            const int kb = ks * 32;
#pragma unroll
            for (int g = 0; g < 4; g++) {
                uint32_t br[4];
                ldsm4(br, Ks + (g * 16 + lbrow) * AST + kb + lbkof);
                mma16f(s[2 * g],     qf[ks], br[0], br[1]);
                mma16f(s[2 * g + 1], qf[ks], br[2], br[3]);
            }
        }

        // softmax (max-free): p = exp2(S*C1 + mask*C2); pack fp16 A-frags
        uint32_t pa[4][4];
#pragma unroll
        for (int nt = 0; nt < 8; nt++) {
            const int col = k0 + nt * 8 + cq * 2;
            float2 mk0 = *(const float2*)(mrow0 + col);
            float2 mk1 = *(const float2*)(mrow1 + col);
            float p0 = ex2f(s[nt][0] * C1 + mk0.x * C2);
            float p1 = ex2f(s[nt][1] * C1 + mk0.y * C2);
            float p2 = ex2f(s[nt][2] * C1 + mk1.x * C2);
            float p3 = ex2f(s[nt][3] * C1 + mk1.y * C2);
            l0 += p0 + p1;
            l1 += p2 + p3;
            const int g = nt >> 1, o2 = (nt & 1) * 2;
            pa[g][o2 + 0] = packh2(p0, p1);
            pa[g][o2 + 1] = packh2(p2, p3);
        }

        // mma2: O[16][64] += P . V  (fp16, 4 k16 steps, ldmatrix B)
#pragma unroll
        for (int ks = 0; ks < 4; ks++) {
            const int kb = ks * 32;
#pragma unroll
            for (int g = 0; g < 4; g++) {
                uint32_t br[4];
                ldsm4(br, Vs + (g * 16 + lbrow) * AST + kb + lbkof);
                mma16f(o[2 * g],     pa[ks], br[0], br[1]);
                mma16f(o[2 * g + 1], pa[ks], br[2], br[3]);
            }
        }
    }

    // Row sums: quad reduce, normalize, store fp32.
    l0 += __shfl_xor_sync(0xffffffffu, l0, 1);
    l0 += __shfl_xor_sync(0xffffffffu, l0, 2);
    l1 += __shfl_xor_sync(0xffffffffu, l1, 1);
    l1 += __shfl_xor_sync(0xffffffffu, l1, 2);
    const float inv0 = 1.0f / l0, inv1 = 1.0f / l1;
    const int qr0 = q0 + m, qr1 = qr0 + 8;
#pragma unroll
    for (int nt = 0; nt < 8; nt++) {
        int dd = nt * 8 + cq * 2;
        *(float2*)(out + ((size_t)qr0 * BATCH + b) * HIDDEN + h * HDIM + dd) =
            make_float2(o[nt][0] * inv0, o[nt][1] * inv0);
        *(float2*)(out + ((size_t)qr1 * BATCH + b) * HIDDEN + h * HDIM + dd) =
            make_float2(o[nt][2] * inv1, o[nt][3] * inv1);
    }
}

// ----------------------------------------------------------------
extern "C" void kernel_launch(void* const* d_in, const int* in_sizes, int n_in,
                              void* d_out, int out_size)
{
    const float* hs   = (const float*)d_in[0];
    const float* mask = (const float*)d_in[1];
    const float* Wq   = (const float*)d_in[2];
    const float* bq   = (const float*)d_in[3];
    const float* Wk   = (const float*)d_in[4];
    const float* bk   = (const float*)d_in[5];
    const float* Wv   = (const float*)d_in[6];
    const float* bv   = (const float*)d_in[7];
    float* out = (float*)d_out;

    cudaFuncSetAttribute(qkv_kernel,
                         cudaFuncAttributeMaxDynamicSharedMemorySize, QKV_SMEM);
    cudaFuncSetAttribute(attn_kernel,
                         cudaFuncAttributeMaxDynamicSharedMemorySize, ATTN_SMEM);

    prep_hs<<<(TOK * HIDDEN / 4) / 256, 256>>>(hs);
    prep_w<<<dim3(HIDDEN / 32, HIDDEN / 32, 3), dim3(32, 8)>>>(Wq, Wk, Wv);

    dim3 g1(HIDDEN / 128, TOK / 256, 3);
    qkv_kernel<<<g1, 512, QKV_SMEM>>>(bq, bk, bv);

    dim3 g2(NH, SEQ / 128);
    attn_kernel<<<g2, 256, ATTN_SMEM>>>(mask, out);
}

// round 9
// speedup vs baseline: 2.1879x; 1.0426x over previous
#include <cuda_runtime.h>
#include <cuda_fp16.h>
#include <cstdint>

#define SEQ     2048
#define BATCH   2
#define HIDDEN  1024
#define NHEAD   16
#define HDIM    64
#define NH      32
#define TOK     4096

// Scratch (device globals).
__device__ __half g_hs[(size_t)TOK * HIDDEN];        // hs, fp16
__device__ __half g_wt[3][HIDDEN * HIDDEN];          // W^T fp16: wt[c][k]
__device__ __half g_q[(size_t)NH * SEQ * HDIM];      // [n][s][d]
__device__ __half g_k[(size_t)NH * SEQ * HDIM];      // [n][s][d]
__device__ __half g_v[(size_t)NH * HDIM * SEQ];      // [n][d][s]
__device__ __half g_mask[(size_t)BATCH * SEQ * SEQ]; // mask * log2(e), fp16

// ---------------------------------------------------------------- helpers
__device__ __forceinline__ float ex2f(float x) {
    float y; asm("ex2.approx.ftz.f32 %0, %1;" : "=f"(y) : "f"(x));
    return y;
}
__device__ __forceinline__ uint32_t packh2(float lo, float hi) {
    __half2 h = __floats2half2_rn(lo, hi);
    return *(uint32_t*)&h;
}
__device__ __forceinline__ void mma16f(float d[4], const uint32_t a[4],
                                       uint32_t b0, uint32_t b1) {
    asm volatile(
        "mma.sync.aligned.m16n8k16.row.col.f32.f16.f16.f32 "
        "{%0,%1,%2,%3}, {%4,%5,%6,%7}, {%8,%9}, {%0,%1,%2,%3};"
        : "+f"(d[0]), "+f"(d[1]), "+f"(d[2]), "+f"(d[3])
        : "r"(a[0]), "r"(a[1]), "r"(a[2]), "r"(a[3]), "r"(b0), "r"(b1));
}
__device__ __forceinline__ void ldsm4(uint32_t r[4], uint32_t addr) {
    asm volatile("ldmatrix.sync.aligned.m8n8.x4.shared.b16 {%0,%1,%2,%3}, [%4];"
        : "=r"(r[0]), "=r"(r[1]), "=r"(r[2]), "=r"(r[3]) : "r"(addr));
}
__device__ __forceinline__ uint32_t smem_u32(const void* p) {
    uint32_t a;
    asm("{ .reg .u64 t; cvta.to.shared.u64 t, %1; cvt.u32.u64 %0, t; }" : "=r"(a) : "l"(p));
    return a;
}
__device__ __forceinline__ void cpa16(uint32_t s, const void* g) {
    asm volatile("cp.async.ca.shared.global [%0], [%1], 16;" :: "r"(s), "l"(g));
}
#define CPA_COMMIT() asm volatile("cp.async.commit_group;" ::: "memory")
#define CPA_WAIT(n)  asm volatile("cp.async.wait_group %0;" :: "n"(n) : "memory")

// ---------------------------------------------------------------- prep
__global__ __launch_bounds__(256) void prep_hs(const float* __restrict__ hs) {
    const size_t i = ((size_t)blockIdx.x * 256 + threadIdx.x) * 4;
    float4 v = *(const float4*)(hs + i);
    __half2* d = (__half2*)(g_hs + i);
    d[0] = __floats2half2_rn(v.x, v.y);
    d[1] = __floats2half2_rn(v.z, v.w);
}
__global__ __launch_bounds__(256) void prep_mask(const float* __restrict__ mask) {
    const float C2 = 1.4426950408889634f;
    const size_t i = ((size_t)blockIdx.x * 256 + threadIdx.x) * 4;
    float4 v = *(const float4*)(mask + i);
    __half2* d = (__half2*)(g_mask + i);
    d[0] = __floats2half2_rn(v.x * C2, v.y * C2);
    d[1] = __floats2half2_rn(v.z * C2, v.w * C2);
}
__global__ void prep_w(const float* __restrict__ Wq, const float* __restrict__ Wk,
                       const float* __restrict__ Wv) {
    __shared__ float t[32][33];
    const float* W = (blockIdx.z == 0) ? Wq : (blockIdx.z == 1) ? Wk : Wv;
    __half* wt = g_wt[blockIdx.z];
    const int k0 = blockIdx.y * 32, c0 = blockIdx.x * 32;
    for (int i = threadIdx.y; i < 32; i += 8)
        t[i][threadIdx.x] = W[(size_t)(k0 + i) * HIDDEN + c0 + threadIdx.x];
    __syncthreads();
    for (int i = threadIdx.y; i < 32; i += 8)
        wt[(size_t)(c0 + i) * HIDDEN + k0 + threadIdx.x] =
            __float2half_rn(t[threadIdx.x][i]);
}

// ---------------------------------------------------------------- QKV GEMM
// CTA 256x128, BK=64 fp16, cp.async double-buffered, ldmatrix fragments.
#define QST       144
#define QKV_A_SZ  (256 * QST)
#define QKV_B_SZ  (128 * QST)
#define QKV_STG   (QKV_A_SZ + QKV_B_SZ)
#define QKV_SMEM  (2 * QKV_STG)

__global__ __launch_bounds__(512, 1) void qkv_kernel(
    const float* __restrict__ bq, const float* __restrict__ bk,
    const float* __restrict__ bv)
{
    extern __shared__ char smq[];
    const uint32_t sbase = smem_u32(smq);

    const int z = blockIdx.z;
    const __half* W   = g_wt[z];
    const float* bias = (z == 0) ? bq : (z == 1) ? bk : bv;

    const int tid = threadIdx.x;
    const int lane = tid & 31, wid = tid >> 5;
    const int wm = wid >> 1, wn = wid & 1;       // 8 x 2
    const int c0 = blockIdx.x * 128;
    const int t0 = blockIdx.y * 256;
    const int r = lane >> 2, cq = lane & 3;
    const int larow = lane & 15;
    const int lakof = (lane >> 4) << 4;
    const int lbrow = ((lane & 16) >> 1) | (lane & 7);
    const int lbkof = (lane & 8) << 1;

    float acc[2][8][4];
#pragma unroll
    for (int i = 0; i < 2; i++)
#pragma unroll
        for (int j = 0; j < 8; j++)
#pragma unroll
            for (int k = 0; k < 4; k++) acc[i][j][k] = 0.f;

    auto issue = [&](int t, int st) {
        const uint32_t ab = sbase + (uint32_t)st * QKV_STG;
        const uint32_t bb = ab + QKV_A_SZ;
#pragma unroll
        for (int j = 0; j < 4; j++) {
            int idx = tid + j * 512;
            int row = idx >> 3, c = idx & 7;
            cpa16(ab + row * QST + c * 16,
                  g_hs + (size_t)(t0 + row) * HIDDEN + t * 64 + c * 8);
        }
#pragma unroll
        for (int j = 0; j < 2; j++) {
            int idx = tid + j * 512;
            int row = idx >> 3, c = idx & 7;
            cpa16(bb + row * QST + c * 16,
                  W + (size_t)(c0 + row) * HIDDEN + t * 64 + c * 8);
        }
        CPA_COMMIT();
    };

    issue(0, 0);
    for (int t = 0; t < 16; t++) {
        const int st = t & 1;
        if (t < 15) { issue(t + 1, 1 - st); CPA_WAIT(1); }
        else        { CPA_WAIT(0); }
        __syncthreads();

        const uint32_t aB = sbase + st * QKV_STG;
        const uint32_t bB = aB + QKV_A_SZ;
#pragma unroll
        for (int ks = 0; ks < 4; ks++) {
            const int kb = ks * 32;
            uint32_t af[2][4], bf[4][4];
#pragma unroll
            for (int mt = 0; mt < 2; mt++)
                ldsm4(af[mt], aB + (wm * 32 + mt * 16 + larow) * QST + kb + lakof);
#pragma unroll
            for (int g = 0; g < 4; g++)
                ldsm4(bf[g], bB + (wn * 64 + g * 16 + lbrow) * QST + kb + lbkof);
#pragma unroll
            for (int mt = 0; mt < 2; mt++)
#pragma unroll
                for (int g = 0; g < 4; g++) {
                    mma16f(acc[mt][2 * g],     af[mt], bf[g][0], bf[g][1]);
                    mma16f(acc[mt][2 * g + 1], af[mt], bf[g][2], bf[g][3]);
                }
        }
        __syncthreads();
    }

    const int c2 = cq * 2;
#pragma unroll
    for (int mt = 0; mt < 2; mt++) {
#pragma unroll
        for (int hf = 0; hf < 2; hf++) {
            int t = t0 + wm * 32 + mt * 16 + hf * 8 + r;
            int s = t >> 1, bb = t & 1;
#pragma unroll
            for (int nf = 0; nf < 8; nf++) {
                int cc = c0 + wn * 64 + nf * 8 + c2;
                int h = cc >> 6, d = cc & 63;
                int nH = bb * NHEAD + h;
                float a0 = acc[mt][nf][hf * 2 + 0] + bias[cc];
                float a1 = acc[mt][nf][hf * 2 + 1] + bias[cc + 1];
                if (z == 2) {
                    g_v[((size_t)nH * HDIM + d) * SEQ + s]     = __float2half_rn(a0);
                    g_v[((size_t)nH * HDIM + d + 1) * SEQ + s] = __float2half_rn(a1);
                } else {
                    __half* dst = (z == 0) ? g_q : g_k;
                    *(__half2*)(dst + ((size_t)nH * SEQ + s) * HDIM + d) =
                        __floats2half2_rn(a0, a1);
                }
            }
        }
    }
}

// ---------------------------------------------------------------- attention
// CTA = 128 threads (4 warps), q-tile 128 (32 q-rows per warp), k-tile 64,
// 2 CTAs/SM. Each K/V ldmatrix fragment feeds TWO 16-row MMAs -> smem read
// traffic per MAC halved vs 16-row warps. P register-resident fp16.
// 3-stage cp.async pipeline, one barrier per ktile.
#define AST   144
#define A_STG (64 * AST)
#define ATTN_SMEM (6 * A_STG)             // 55296 B

__global__ __launch_bounds__(128, 2) void attn_kernel(float* __restrict__ out)
{
    extern __shared__ char sma[];
    const uint32_t sb = smem_u32(sma);

    const int n  = blockIdx.x;            // head-instance (b*16+h)
    const int q0 = blockIdx.y * 128;
    const int b = n >> 4, h = n & 15;
    const int tid = threadIdx.x;
    const int lane = tid & 31, wid = tid >> 5;
    const int r = lane >> 2, cq = lane & 3;
    const int m0 = wid * 32 + r;          // rows m0, +8 (rg0); +16, +24 (rg1)
    const int lbrow = ((lane & 16) >> 1) | (lane & 7);
    const int lbkof = (lane & 8) << 1;

    const __half* qg = g_q + (size_t)n * SEQ * HDIM;
    const __half* kg = g_k + (size_t)n * SEQ * HDIM;
    const __half* vg = g_v + (size_t)n * HDIM * SEQ;
    const __half* mk = g_mask + ((size_t)b * SEQ + q0 + m0) * SEQ;

    // Q fragments: 2 row-groups x 4 k16-steps.
    uint32_t qf[2][4][4];
#pragma unroll
    for (int rg = 0; rg < 2; rg++)
#pragma unroll
        for (int ks = 0; ks < 4; ks++) {
            const int dk = ks * 16 + cq * 2;
            const size_t r0 = (size_t)(q0 + m0 + rg * 16) * HDIM;
            qf[rg][ks][0] = *(const uint32_t*)(qg + r0 + dk);
            qf[rg][ks][1] = *(const uint32_t*)(qg + r0 + 8 * HDIM + dk);
            qf[rg][ks][2] = *(const uint32_t*)(qg + r0 + dk + 8);
            qf[rg][ks][3] = *(const uint32_t*)(qg + r0 + 8 * HDIM + dk + 8);
        }

    float o[2][8][4];
#pragma unroll
    for (int rg = 0; rg < 2; rg++)
#pragma unroll
        for (int i = 0; i < 8; i++)
#pragma unroll
            for (int j = 0; j < 4; j++) o[rg][i][j] = 0.f;
    float lA[2] = {0.f, 0.f}, lB[2] = {0.f, 0.f};

    const float C1 = 0.18033688011112042f;   // log2(e)/8

    auto issueKV = [&](int kt) {
        if (kt >= SEQ / 64) return;
        const int st = kt % 3;
        const int k0 = kt * 64;
        const uint32_t kb = sb + st * A_STG;
        const uint32_t vb = sb + 3 * A_STG + st * A_STG;
#pragma unroll
        for (int j = 0; j < 4; j++) {
            int idx = tid + j * 128;
            int row = idx >> 3, c = idx & 7;
            cpa16(kb + row * AST + c * 16,
                  kg + (size_t)(k0 + row) * HDIM + c * 8);
        }
#pragma unroll
        for (int j = 0; j < 4; j++) {
            int idx = tid + j * 128;
            int row = idx >> 3, c = idx & 7;
            cpa16(vb + row * AST + c * 16,
                  vg + (size_t)row * SEQ + k0 + c * 8);
        }
        CPA_COMMIT();
    };

    issueKV(0);
    issueKV(1);
    for (int kt = 0; kt < SEQ / 64; kt++) {
        const int st = kt % 3;
        const int k0 = kt * 64;
        if (kt < SEQ / 64 - 1) { CPA_WAIT(1); } else { CPA_WAIT(0); }
        __syncthreads();
        issueKV(kt + 2);

        const uint32_t Ks = sb + st * A_STG;
        const uint32_t Vs = sb + 3 * A_STG + st * A_STG;

        // mma1: S[32][64] = Q . K^T; each K fragment used by both row-groups.
        float s[2][8][4];
#pragma unroll
        for (int rg = 0; rg < 2; rg++)
#pragma unroll
            for (int i = 0; i < 8; i++)
#pragma unroll
                for (int j = 0; j < 4; j++) s[rg][i][j] = 0.f;
#pragma unroll
        for (int ks = 0; ks < 4; ks++) {
            const int kb = ks * 32;
#pragma unroll
            for (int g = 0; g < 4; g++) {
                uint32_t br[4];
                ldsm4(br, Ks + (g * 16 + lbrow) * AST + kb + lbkof);
#pragma unroll
                for (int rg = 0; rg < 2; rg++) {
                    mma16f(s[rg][2 * g],     qf[rg][ks], br[0], br[1]);
                    mma16f(s[rg][2 * g + 1], qf[rg][ks], br[2], br[3]);
                }
            }
        }

        // softmax (max-free): p = exp2(S*C1 + mask2), mask2 pre-scaled fp16.
        uint32_t pa[2][4][4];
#pragma unroll
        for (int rg = 0; rg < 2; rg++)
#pragma unroll
            for (int nt = 0; nt < 8; nt++) {
                const size_t col = k0 + nt * 8 + cq * 2;
                const __half* mrow = mk + (size_t)rg * 16 * SEQ + col;
                float2 mk0 = __half22float2(*(const __half2*)(mrow));
                float2 mk1 = __half22float2(*(const __half2*)(mrow + 8 * SEQ));
                float p0 = ex2f(s[rg][nt][0] * C1 + mk0.x);
                float p1 = ex2f(s[rg][nt][1] * C1 + mk0.y);
                float p2 = ex2f(s[rg][nt][2] * C1 + mk1.x);
                float p3 = ex2f(s[rg][nt][3] * C1 + mk1.y);
                lA[rg] += p0 + p1;
                lB[rg] += p2 + p3;
                const int g = nt >> 1, o2 = (nt & 1) * 2;
                pa[rg][g][o2 + 0] = packh2(p0, p1);
                pa[rg][g][o2 + 1] = packh2(p2, p3);
            }

        // mma2: O[32][64] += P . V; each V fragment used by both row-groups.
#pragma unroll
        for (int ks = 0; ks < 4; ks++) {
            const int kb = ks * 32;
#pragma unroll
            for (int g = 0; g < 4; g++) {
                uint32_t br[4];
                ldsm4(br, Vs + (g * 16 + lbrow) * AST + kb + lbkof);
#pragma unroll
                for (int rg = 0; rg < 2; rg++) {
                    mma16f(o[rg][2 * g],     pa[rg][ks], br[0], br[1]);
                    mma16f(o[rg][2 * g + 1], pa[rg][ks], br[2], br[3]);
                }
            }
        }
    }

    // Row sums: quad reduce, normalize, store fp32.
#pragma unroll
    for (int rg = 0; rg < 2; rg++) {
        float l0 = lA[rg], l1 = lB[rg];
        l0 += __shfl_xor_sync(0xffffffffu, l0, 1);
        l0 += __shfl_xor_sync(0xffffffffu, l0, 2);
        l1 += __shfl_xor_sync(0xffffffffu, l1, 1);
        l1 += __shfl_xor_sync(0xffffffffu, l1, 2);
        const float inv0 = 1.0f / l0, inv1 = 1.0f / l1;
        const int qr0 = q0 + m0 + rg * 16, qr1 = qr0 + 8;
#pragma unroll
        for (int nt = 0; nt < 8; nt++) {
            int dd = nt * 8 + cq * 2;
            *(float2*)(out + ((size_t)qr0 * BATCH + b) * HIDDEN + h * HDIM + dd) =
                make_float2(o[rg][nt][0] * inv0, o[rg][nt][1] * inv0);
            *(float2*)(out + ((size_t)qr1 * BATCH + b) * HIDDEN + h * HDIM + dd) =
                make_float2(o[rg][nt][2] * inv1, o[rg][nt][3] * inv1);
        }
    }
}

// ----------------------------------------------------------------
extern "C" void kernel_launch(void* const* d_in, const int* in_sizes, int n_in,
                              void* d_out, int out_size)
{
    const float* hs   = (const float*)d_in[0];
    const float* mask = (const float*)d_in[1];
    const float* Wq   = (const float*)d_in[2];
    const float* bq   = (const float*)d_in[3];
    const float* Wk   = (const float*)d_in[4];
    const float* bk   = (const float*)d_in[5];
    const float* Wv   = (const float*)d_in[6];
    const float* bv   = (const float*)d_in[7];
    float* out = (float*)d_out;

    cudaFuncSetAttribute(qkv_kernel,
                         cudaFuncAttributeMaxDynamicSharedMemorySize, QKV_SMEM);
    cudaFuncSetAttribute(attn_kernel,
                         cudaFuncAttributeMaxDynamicSharedMemorySize, ATTN_SMEM);

    prep_hs<<<(TOK * HIDDEN / 4) / 256, 256>>>(hs);
    prep_mask<<<((size_t)BATCH * SEQ * SEQ / 4) / 256, 256>>>(mask);
    prep_w<<<dim3(HIDDEN / 32, HIDDEN / 32, 3), dim3(32, 8)>>>(Wq, Wk, Wv);

    dim3 g1(HIDDEN / 128, TOK / 256, 3);
    qkv_kernel<<<g1, 512, QKV_SMEM>>>(bq, bk, bv);

    dim3 g2(NH, SEQ / 128);
    attn_kernel<<<g2, 128, ATTN_SMEM>>>(out);
}